// round 7
// baseline (speedup 1.0000x reference)
#include <cuda_runtime.h>

// Collapsed math: out[b,c] = softmax_c( d*r/1000 + d + r ),
// r = x[b,0,c], d = x[b,1,c]; logits in [0, 2.001] -> no max pass needed.
//
// Persistent warp-per-row version:
//   - grid = 148 SMs * 6 CTAs, each warp grid-strides over rows
//   - no wave transitions; loads of row i+1 overlap epilogue of row i
//   - warp-only shfl reduction, no smem, no __syncthreads
//   - __ldcs/__stcs streaming (zero-reuse), 16B vector accesses

#define NUM_CLASSES 1000
#define VEC_PER_ROW (NUM_CLASSES / 4)      // 250 float4 per row per tensor
#define ROW_VEC_STRIDE (2 * VEC_PER_ROW)   // 500 float4 per (2,1000) row
#define THREADS 256
#define ITERS 8                            // ceil(250/32)
#define GRID_CTAS (148 * 6)

__global__ __launch_bounds__(THREADS) void tmc_softmax_persist(
    const float4* __restrict__ x4, float4* __restrict__ out4, int nrows)
{
    const int lane = threadIdx.x & 31;
    const int gwarp = (blockIdx.x * THREADS + threadIdx.x) >> 5;
    const int nwarps = (gridDim.x * THREADS) >> 5;

    for (size_t row = gwarp; row < (size_t)nrows; row += nwarps) {
        const float4* __restrict__ rgb = x4 + row * ROW_VEC_STRIDE;
        const float4* __restrict__ dep = rgb + VEC_PER_ROW;
        float4* __restrict__ out = out4 + row * VEC_PER_ROW;

        float4 ev[ITERS];
        float local = 0.f;

        #pragma unroll
        for (int i = 0; i < ITERS; i++) {
            const int idx = lane + 32 * i;
            if (idx < VEC_PER_ROW) {
                float4 r = __ldcs(&rgb[idx]);
                float4 d = __ldcs(&dep[idx]);
                float4 e;
                e.x = __expf(fmaf(d.x * r.x, 1e-3f, d.x + r.x));
                e.y = __expf(fmaf(d.y * r.y, 1e-3f, d.y + r.y));
                e.z = __expf(fmaf(d.z * r.z, 1e-3f, d.z + r.z));
                e.w = __expf(fmaf(d.w * r.w, 1e-3f, d.w + r.w));
                ev[i] = e;
                local += (e.x + e.y) + (e.z + e.w);
            }
        }

        #pragma unroll
        for (int off = 16; off > 0; off >>= 1)
            local += __shfl_xor_sync(0xFFFFFFFFu, local, off);

        const float inv = 1.0f / local;

        #pragma unroll
        for (int i = 0; i < ITERS; i++) {
            const int idx = lane + 32 * i;
            if (idx < VEC_PER_ROW) {
                float4 o;
                o.x = ev[i].x * inv;
                o.y = ev[i].y * inv;
                o.z = ev[i].z * inv;
                o.w = ev[i].w * inv;
                __stcs(&out[idx], o);
            }
        }
    }
}

extern "C" void kernel_launch(void* const* d_in, const int* in_sizes, int n_in,
                              void* d_out, int out_size)
{
    const float4* x4 = (const float4*)d_in[0];
    float4* out4 = (float4*)d_out;
    const int batch = in_sizes[0] / (2 * NUM_CLASSES);   // 65536
    tmc_softmax_persist<<<GRID_CTAS, THREADS>>>(x4, out4, batch);
}

// round 8
// speedup vs baseline: 1.0364x; 1.0364x over previous
#include <cuda_runtime.h>

// Collapsed math: out[b,c] = softmax_c( d*r/1000 + d + r ),
// r = x[b,0,c], d = x[b,1,c]; logits in [0, 2.001] -> no max pass needed.
//
// Warp-per-row, non-persistent (best-known shape from R3):
//   - one warp owns one full row (250 float4 = 1000 classes)
//   - loads front-batched (16x LDG.128 per warp before any exp)
//   - warp-only shfl reduction; no smem, no __syncthreads
//   - __ldcs/__stcs streaming hints (zero-reuse stream)
//   - 512 threads/CTA -> 16 rows per CTA, grid 4096

#define NUM_CLASSES 1000
#define VEC_PER_ROW (NUM_CLASSES / 4)      // 250 float4 per row per tensor
#define ROW_VEC_STRIDE (2 * VEC_PER_ROW)   // 500 float4 per (2,1000) row
#define THREADS 512
#define ROWS_PER_CTA (THREADS / 32)        // 16
#define ITERS 8                            // ceil(250/32)

__global__ __launch_bounds__(THREADS) void tmc_softmax_warprow(
    const float4* __restrict__ x4, float4* __restrict__ out4)
{
    const int warp = threadIdx.x >> 5;
    const int lane = threadIdx.x & 31;
    const size_t row = (size_t)blockIdx.x * ROWS_PER_CTA + warp;

    const float4* __restrict__ rgb = x4 + row * ROW_VEC_STRIDE;
    const float4* __restrict__ dep = rgb + VEC_PER_ROW;
    float4* __restrict__ out = out4 + row * VEC_PER_ROW;

    // Front-batch all loads first to maximize outstanding LDG.128 (MLP).
    float4 rr[ITERS], dd[ITERS];
    #pragma unroll
    for (int i = 0; i < ITERS; i++) {
        const int idx = lane + 32 * i;
        if (idx < VEC_PER_ROW) {
            rr[i] = __ldcs(&rgb[idx]);
            dd[i] = __ldcs(&dep[idx]);
        }
    }

    float4 ev[ITERS];
    float local = 0.f;
    #pragma unroll
    for (int i = 0; i < ITERS; i++) {
        const int idx = lane + 32 * i;
        if (idx < VEC_PER_ROW) {
            float4 r = rr[i], d = dd[i], e;
            e.x = __expf(fmaf(d.x * r.x, 1e-3f, d.x + r.x));
            e.y = __expf(fmaf(d.y * r.y, 1e-3f, d.y + r.y));
            e.z = __expf(fmaf(d.z * r.z, 1e-3f, d.z + r.z));
            e.w = __expf(fmaf(d.w * r.w, 1e-3f, d.w + r.w));
            ev[i] = e;
            local += (e.x + e.y) + (e.z + e.w);
        }
    }

    // Warp-only reduction: no barriers, no smem.
    #pragma unroll
    for (int off = 16; off > 0; off >>= 1)
        local += __shfl_xor_sync(0xFFFFFFFFu, local, off);

    const float inv = 1.0f / local;

    #pragma unroll
    for (int i = 0; i < ITERS; i++) {
        const int idx = lane + 32 * i;
        if (idx < VEC_PER_ROW) {
            float4 o;
            o.x = ev[i].x * inv;
            o.y = ev[i].y * inv;
            o.z = ev[i].z * inv;
            o.w = ev[i].w * inv;
            __stcs(&out[idx], o);
        }
    }
}

extern "C" void kernel_launch(void* const* d_in, const int* in_sizes, int n_in,
                              void* d_out, int out_size)
{
    const float4* x4 = (const float4*)d_in[0];
    float4* out4 = (float4*)d_out;
    const int batch = in_sizes[0] / (2 * NUM_CLASSES);   // 65536
    tmc_softmax_warprow<<<batch / ROWS_PER_CTA, THREADS>>>(x4, out4);
}

// round 9
// speedup vs baseline: 1.0786x; 1.0407x over previous
#include <cuda_runtime.h>

// Collapsed math: out[b,c] = softmax_c( d*r/1000 + d + r ),
// r = x[b,0,c], d = x[b,1,c]; logits in [0, 2.001] -> no max pass needed.
//
// Best-known shape (R3): warp-per-row, 256-thread CTAs, grid 8192.
//   - one warp owns one full row (250 float4 = 1000 classes)
//   - iterations 0..6 unconditional (idx <= 223 < 250); only iter 7 predicated
//   - warp-only shfl reduction; no smem, no __syncthreads
//   - __ldcs/__stcs streaming hints (zero-reuse stream), 16B accesses

#define NUM_CLASSES 1000
#define VEC_PER_ROW (NUM_CLASSES / 4)      // 250 float4 per row per tensor
#define ROW_VEC_STRIDE (2 * VEC_PER_ROW)   // 500 float4 per (2,1000) row
#define THREADS 256
#define ROWS_PER_CTA (THREADS / 32)        // 8
#define FULL_ITERS 7                       // lane + 32*6 = 223 < 250 always

__device__ __forceinline__ float4 ev4(float4 r, float4 d)
{
    float4 e;
    e.x = __expf(fmaf(d.x * r.x, 1e-3f, d.x + r.x));
    e.y = __expf(fmaf(d.y * r.y, 1e-3f, d.y + r.y));
    e.z = __expf(fmaf(d.z * r.z, 1e-3f, d.z + r.z));
    e.w = __expf(fmaf(d.w * r.w, 1e-3f, d.w + r.w));
    return e;
}

__global__ __launch_bounds__(THREADS) void tmc_softmax_warprow(
    const float4* __restrict__ x4, float4* __restrict__ out4)
{
    const int warp = threadIdx.x >> 5;
    const int lane = threadIdx.x & 31;
    const size_t row = (size_t)blockIdx.x * ROWS_PER_CTA + warp;

    const float4* __restrict__ rgb = x4 + row * ROW_VEC_STRIDE;
    const float4* __restrict__ dep = rgb + VEC_PER_ROW;
    float4* __restrict__ out = out4 + row * VEC_PER_ROW;

    const bool tail = (lane + 32 * FULL_ITERS) < VEC_PER_ROW;   // lane < 26

    float4 ev[FULL_ITERS + 1];
    float local = 0.f;

    #pragma unroll
    for (int i = 0; i < FULL_ITERS; i++) {
        const int idx = lane + 32 * i;
        float4 e = ev4(__ldcs(&rgb[idx]), __ldcs(&dep[idx]));
        ev[i] = e;
        local += (e.x + e.y) + (e.z + e.w);
    }
    if (tail) {
        const int idx = lane + 32 * FULL_ITERS;
        float4 e = ev4(__ldcs(&rgb[idx]), __ldcs(&dep[idx]));
        ev[FULL_ITERS] = e;
        local += (e.x + e.y) + (e.z + e.w);
    }

    // Warp-only reduction: no barriers, no smem.
    #pragma unroll
    for (int off = 16; off > 0; off >>= 1)
        local += __shfl_xor_sync(0xFFFFFFFFu, local, off);

    const float inv = 1.0f / local;

    #pragma unroll
    for (int i = 0; i < FULL_ITERS; i++) {
        const int idx = lane + 32 * i;
        float4 o;
        o.x = ev[i].x * inv;
        o.y = ev[i].y * inv;
        o.z = ev[i].z * inv;
        o.w = ev[i].w * inv;
        __stcs(&out[idx], o);
    }
    if (tail) {
        const int idx = lane + 32 * FULL_ITERS;
        float4 o;
        o.x = ev[FULL_ITERS].x * inv;
        o.y = ev[FULL_ITERS].y * inv;
        o.z = ev[FULL_ITERS].z * inv;
        o.w = ev[FULL_ITERS].w * inv;
        __stcs(&out[idx], o);
    }
}

extern "C" void kernel_launch(void* const* d_in, const int* in_sizes, int n_in,
                              void* d_out, int out_size)
{
    const float4* x4 = (const float4*)d_in[0];
    float4* out4 = (float4*)d_out;
    const int batch = in_sizes[0] / (2 * NUM_CLASSES);   // 65536
    tmc_softmax_warprow<<<batch / ROWS_PER_CTA, THREADS>>>(x4, out4);
}

// round 10
// speedup vs baseline: 1.0810x; 1.0022x over previous
#include <cuda_runtime.h>

// Collapsed math: out[b,c] = softmax_c( d*r/1000 + d + r ),
// r = x[b,0,c], d = x[b,1,c]; logits in [0, 2.001] -> no max pass needed.
//
// Warp-per-row, 128-thread CTAs (4 rows/CTA), grid 16384:
//   - finer CTA granularity for work-distributor backfill (8192 -> 16384 units)
//   - one warp owns one full row (250 float4 = 1000 classes)
//   - iterations 0..6 unconditional; only iter 7 predicated (lane < 26)
//   - warp-only shfl reduction; no smem, no __syncthreads
//   - __ldcs/__stcs streaming hints (zero-reuse stream), 16B accesses

#define NUM_CLASSES 1000
#define VEC_PER_ROW (NUM_CLASSES / 4)      // 250 float4 per row per tensor
#define ROW_VEC_STRIDE (2 * VEC_PER_ROW)   // 500 float4 per (2,1000) row
#define THREADS 128
#define ROWS_PER_CTA (THREADS / 32)        // 4
#define FULL_ITERS 7                       // lane + 32*6 = 223 < 250 always

__device__ __forceinline__ float4 ev4(float4 r, float4 d)
{
    float4 e;
    e.x = __expf(fmaf(d.x * r.x, 1e-3f, d.x + r.x));
    e.y = __expf(fmaf(d.y * r.y, 1e-3f, d.y + r.y));
    e.z = __expf(fmaf(d.z * r.z, 1e-3f, d.z + r.z));
    e.w = __expf(fmaf(d.w * r.w, 1e-3f, d.w + r.w));
    return e;
}

__global__ __launch_bounds__(THREADS) void tmc_softmax_warprow(
    const float4* __restrict__ x4, float4* __restrict__ out4)
{
    const int warp = threadIdx.x >> 5;
    const int lane = threadIdx.x & 31;
    const size_t row = (size_t)blockIdx.x * ROWS_PER_CTA + warp;

    const float4* __restrict__ rgb = x4 + row * ROW_VEC_STRIDE;
    const float4* __restrict__ dep = rgb + VEC_PER_ROW;
    float4* __restrict__ out = out4 + row * VEC_PER_ROW;

    const bool tail = (lane + 32 * FULL_ITERS) < VEC_PER_ROW;   // lane < 26

    float4 ev[FULL_ITERS + 1];
    float local = 0.f;

    #pragma unroll
    for (int i = 0; i < FULL_ITERS; i++) {
        const int idx = lane + 32 * i;
        float4 e = ev4(__ldcs(&rgb[idx]), __ldcs(&dep[idx]));
        ev[i] = e;
        local += (e.x + e.y) + (e.z + e.w);
    }
    if (tail) {
        const int idx = lane + 32 * FULL_ITERS;
        float4 e = ev4(__ldcs(&rgb[idx]), __ldcs(&dep[idx]));
        ev[FULL_ITERS] = e;
        local += (e.x + e.y) + (e.z + e.w);
    }

    // Warp-only reduction: no barriers, no smem.
    #pragma unroll
    for (int off = 16; off > 0; off >>= 1)
        local += __shfl_xor_sync(0xFFFFFFFFu, local, off);

    const float inv = 1.0f / local;

    #pragma unroll
    for (int i = 0; i < FULL_ITERS; i++) {
        const int idx = lane + 32 * i;
        float4 o;
        o.x = ev[i].x * inv;
        o.y = ev[i].y * inv;
        o.z = ev[i].z * inv;
        o.w = ev[i].w * inv;
        __stcs(&out[idx], o);
    }
    if (tail) {
        const int idx = lane + 32 * FULL_ITERS;
        float4 o;
        o.x = ev[FULL_ITERS].x * inv;
        o.y = ev[FULL_ITERS].y * inv;
        o.z = ev[FULL_ITERS].z * inv;
        o.w = ev[FULL_ITERS].w * inv;
        __stcs(&out[idx], o);
    }
}

extern "C" void kernel_launch(void* const* d_in, const int* in_sizes, int n_in,
                              void* d_out, int out_size)
{
    const float4* x4 = (const float4*)d_in[0];
    float4* out4 = (float4*)d_out;
    const int batch = in_sizes[0] / (2 * NUM_CLASSES);   // 65536
    tmc_softmax_warprow<<<batch / ROWS_PER_CTA, THREADS>>>(x4, out4);
}